// round 10
// baseline (speedup 1.0000x reference)
#include <cuda_runtime.h>

// Problem constants
#define NP    196           // patches per image
#define NCG   49            // NP/4 column groups
#define NF4   (NP * NCG)    // 9604 float4 elements in one adj matrix
#define TPB   392           // = 2*196 = 8*49: stride keeps cg fixed per thread
#define IPC   2             // images per CTA
#define HID   32
#define NCLS  10
#define TSQRT 0.894427191f  // sqrt(0.8)

__device__ __forceinline__ float dot4(float4 a, float4 b) {
    return a.x * b.x + a.y * b.y + a.z * b.z + a.w * b.w;
}

// fid = dot^2 >= 0.8  <=>  |dot| >= sqrt(0.8); FSETP applies |.| for free
__device__ __forceinline__ float classify(float d) {
    return (fabsf(d) >= TSQRT) ? 1.0f : 0.0f;
}

__global__ __launch_bounds__(TPB, 2)
void quanv_graph_kernel(const float* __restrict__ x,
                        const float* __restrict__ W1,
                        const float* __restrict__ b1,
                        const float* __restrict__ W2,
                        const float* __restrict__ b2,
                        float* __restrict__ out,
                        float* __restrict__ adj)
{
    __shared__ float4 an_s[IPC][NP];   // normalized vectors, per image
    __shared__ float4 vec_s[IPC][NP];  // raw vectors (for pooling), per image

    const int tid = threadIdx.x;
    const int b0  = blockIdx.x * IPC;  // first image this CTA owns

    // ---- Phase 1: both images' patch expectations in ONE sweep ----
    {
        const int img = (tid >= NP) ? 1 : 0;
        const int p   = tid - img * NP;
        const float4 v = reinterpret_cast<const float4*>(x)[(size_t)(b0 + img) * NP + p];
        float c0 = cosf(v.x + 0.5f);
        float c1 = c0 * cosf(v.y + 0.5f);
        float c2 = c1 * cosf(v.z + 0.5f);
        float c3 = c2 * cosf(v.w + 0.5f);
        vec_s[img][p] = make_float4(c0, c1, c2, c3);
        float n   = sqrtf(c0 * c0 + c1 * c1 + c2 * c2 + c3 * c3);
        float inv = 1.0f / (n + 1e-12f);
        an_s[img][p] = make_float4(c0 * inv, c1 * inv, c2 * inv, c3 * inv);
    }
    __syncthreads();

    const int warp = tid >> 5;
    const int lane = tid & 31;

    // ---- MLP heads: warp 0 -> image 0, warp 1 -> image 1 (lanes 0..9) ----
    if (warp < IPC && lane < NCLS) {
        const int img = warp;
        float px = 0.f, py = 0.f, pz = 0.f, pw = 0.f;
        #pragma unroll 4
        for (int p = 0; p < NP; ++p) {
            float4 v = vec_s[img][p];   // warp-uniform address -> broadcast
            px += v.x; py += v.y; pz += v.z; pw += v.w;
        }
        const float s = 1.0f / (float)NP;
        px *= s; py *= s; pz *= s; pw *= s;
        float acc = b2[lane];
        #pragma unroll 4
        for (int h = 0; h < HID; ++h) {
            float hh = b1[h] + px * W1[h * 4 + 0] + py * W1[h * 4 + 1]
                             + pz * W1[h * 4 + 2] + pw * W1[h * 4 + 3];
            acc += hh * W2[lane * HID + h];
        }
        out[(size_t)(b0 + img) * NCLS + lane] = acc;
    }

    // ---- Phase 2: FUSED adjacency for both images ----
    // One loop, two independent store streams: per iteration the warp issues
    // two back-to-back STG.128 runs (img0 and img1 at the same flat offset),
    // doubling outstanding stores without extra occupancy. Loop bookkeeping
    // and the diagonal predicate (same row/cg for both images) are shared.
    {
        const int cg = tid % NCG;
        int row      = tid / NCG;     // 0..7

        const float4* an0 = an_s[0];
        const float4* an1 = an_s[1];

        const float4 u00 = an0[4 * cg + 0], u01 = an0[4 * cg + 1];
        const float4 u02 = an0[4 * cg + 2], u03 = an0[4 * cg + 3];
        const float4 u10 = an1[4 * cg + 0], u11 = an1[4 * cg + 1];
        const float4 u12 = an1[4 * cg + 2], u13 = an1[4 * cg + 3];

        float4* __restrict__ adj40 =
            reinterpret_cast<float4*>(adj + (size_t)b0 * (NP * NP));
        float4* __restrict__ adj41 = adj40 + NF4;

        for (int flat = tid; flat < NF4; flat += TPB, row += 8) {
            const float4 a0 = an0[row];   // <=2 distinct rows per warp
            const float4 a1 = an1[row];

            float4 r0 = make_float4(classify(dot4(a0, u00)), classify(dot4(a0, u01)),
                                    classify(dot4(a0, u02)), classify(dot4(a0, u03)));
            float4 r1 = make_float4(classify(dot4(a1, u10)), classify(dot4(a1, u11)),
                                    classify(dot4(a1, u12)), classify(dot4(a1, u13)));

            if ((row >> 2) == cg) {       // self-edge diagonal, same slot both imgs
                const int c = row & 3;
                if      (c == 0) { r0.x = 0.f; r1.x = 0.f; }
                else if (c == 1) { r0.y = 0.f; r1.y = 0.f; }
                else if (c == 2) { r0.z = 0.f; r1.z = 0.f; }
                else             { r0.w = 0.f; r1.w = 0.f; }
            }

            __stcs(adj40 + flat, r0);     // two independent streams ->
            __stcs(adj41 + flat, r1);     // 2x outstanding stores per warp
        }
    }
}

extern "C" void kernel_launch(void* const* d_in, const int* in_sizes, int n_in,
                              void* d_out, int out_size)
{
    const float* x  = (const float*)d_in[0];   // [B,1,28,28]
    const float* W1 = (const float*)d_in[1];   // [32,4]
    const float* b1 = (const float*)d_in[2];   // [32]
    const float* W2 = (const float*)d_in[3];   // [10,32]
    const float* b2 = (const float*)d_in[4];   // [10]

    const int B = in_sizes[0] / 784;           // 4096

    float* out = (float*)d_out;                // [B,10] first
    float* adj = (float*)d_out + (size_t)B * NCLS;  // then [B,196,196]

    quanv_graph_kernel<<<B / IPC, TPB>>>(x, W1, b1, W2, b2, out, adj);
}

// round 11
// speedup vs baseline: 1.0003x; 1.0003x over previous
#include <cuda_runtime.h>

// Problem constants
#define NP    196           // patches per image
#define NCG   49            // NP/4 column groups
#define NF4   (NP * NCG)    // 9604 float4 elements in one adj matrix
#define TPB   392           // = 2*196 = 8*49: stride keeps cg fixed per thread
#define IPC   2             // images per pair (per CTA lap)
#define HID   32
#define NCLS  10
#define TSQRT 0.894427191f  // sqrt(0.8)

__device__ __forceinline__ float dot4(float4 a, float4 b) {
    return a.x * b.x + a.y * b.y + a.z * b.z + a.w * b.w;
}

// fid = dot^2 >= 0.8  <=>  |dot| >= sqrt(0.8); FSETP applies |.| for free
__device__ __forceinline__ float classify(float d) {
    return (fabsf(d) >= TSQRT) ? 1.0f : 0.0f;
}

__global__ __launch_bounds__(TPB, 2)
void quanv_graph_kernel(const float* __restrict__ x,
                        const float* __restrict__ W1,
                        const float* __restrict__ b1,
                        const float* __restrict__ W2,
                        const float* __restrict__ b2,
                        float* __restrict__ out,
                        float* __restrict__ adj,
                        int npairs, int stride)
{
    // double-buffered per-pair state: 2 x 2 x 196 x 16B x 2 arrays = 25 KB
    __shared__ float4 an_s[2][IPC][NP];   // normalized vectors
    __shared__ float4 vec_s[2][IPC][NP];  // raw vectors (for pooling)

    const int tid  = threadIdx.x;
    const int img  = (tid >= NP) ? 1 : 0;     // this thread's patch slot
    const int p    = tid - img * NP;
    const int warp = tid >> 5;
    const int lane = tid & 31;
    const int cg   = tid % NCG;               // fixed column group
    const int row0 = tid / NCG;               // 0..7

    int pair = blockIdx.x;
    if (pair >= npairs) return;

    // ---- prologue: load + convert first pair into buffer 0 ----
    // a pair = 2*784 floats = 392 float4, contiguous: perfectly coalesced
    float4 v = reinterpret_cast<const float4*>(x)[(size_t)pair * TPB + tid];
    int buf = 0;
    {
        float c0 = cosf(v.x + 0.5f);
        float c1 = c0 * cosf(v.y + 0.5f);
        float c2 = c1 * cosf(v.z + 0.5f);
        float c3 = c2 * cosf(v.w + 0.5f);
        vec_s[buf][img][p] = make_float4(c0, c1, c2, c3);
        float n   = sqrtf(c0 * c0 + c1 * c1 + c2 * c2 + c3 * c3);
        float inv = 1.0f / (n + 1e-12f);
        an_s[buf][img][p] = make_float4(c0 * inv, c1 * inv, c2 * inv, c3 * inv);
    }
    __syncthreads();

    while (true) {
        const int next = pair + stride;
        const bool has_next = (next < npairs);

        // ---- prefetch NEXT pair's x now; consumed after the store loop ----
        float4 vn;
        if (has_next)
            vn = reinterpret_cast<const float4*>(x)[(size_t)next * TPB + tid];

        // ---- MLP heads: warp 0 -> image 0, warp 1 -> image 1 ----
        if (warp < IPC && lane < NCLS) {
            const int mi = warp;
            float px = 0.f, py = 0.f, pz = 0.f, pw = 0.f;
            #pragma unroll 4
            for (int q = 0; q < NP; ++q) {
                float4 w = vec_s[buf][mi][q];   // warp-uniform -> broadcast
                px += w.x; py += w.y; pz += w.z; pw += w.w;
            }
            const float s = 1.0f / (float)NP;
            px *= s; py *= s; pz *= s; pw *= s;
            float acc = b2[lane];
            #pragma unroll 4
            for (int h = 0; h < HID; ++h) {
                float hh = b1[h] + px * W1[h * 4 + 0] + py * W1[h * 4 + 1]
                                 + pz * W1[h * 4 + 2] + pw * W1[h * 4 + 3];
                acc += hh * W2[lane * HID + h];
            }
            out[(size_t)(pair * IPC + mi) * NCLS + lane] = acc;
        }

        // ---- adjacency for both images (R8 hot loop, verbatim) ----
        #pragma unroll
        for (int mi = 0; mi < IPC; ++mi) {
            const float4* an = an_s[buf][mi];

            const float4 u0 = an[4 * cg + 0];
            const float4 u1 = an[4 * cg + 1];
            const float4 u2 = an[4 * cg + 2];
            const float4 u3 = an[4 * cg + 3];

            float4* __restrict__ adj4 =
                reinterpret_cast<float4*>(adj + (size_t)(pair * IPC + mi) * (NP * NP));

            int row = row0;
            for (int flat = tid; flat < NF4; flat += TPB, row += 8) {
                const float4 a = an[row];   // <=2 distinct rows per warp
                float4 r = make_float4(classify(dot4(a, u0)), classify(dot4(a, u1)),
                                       classify(dot4(a, u2)), classify(dot4(a, u3)));
                if ((row >> 2) == cg) {     // self-edge diagonal in this group
                    const int c = row & 3;
                    if      (c == 0) r.x = 0.f;
                    else if (c == 1) r.y = 0.f;
                    else if (c == 2) r.z = 0.f;
                    else             r.w = 0.f;
                }
                __stcs(adj4 + flat, r);     // evict-first: write-once data
            }
        }

        if (!has_next) break;

        // ---- convert prefetched pair into the other buffer ----
        {
            const int nb = buf ^ 1;
            float c0 = cosf(vn.x + 0.5f);
            float c1 = c0 * cosf(vn.y + 0.5f);
            float c2 = c1 * cosf(vn.z + 0.5f);
            float c3 = c2 * cosf(vn.w + 0.5f);
            vec_s[nb][img][p] = make_float4(c0, c1, c2, c3);
            float n   = sqrtf(c0 * c0 + c1 * c1 + c2 * c2 + c3 * c3);
            float inv = 1.0f / (n + 1e-12f);
            an_s[nb][img][p] = make_float4(c0 * inv, c1 * inv, c2 * inv, c3 * inv);
        }
        __syncthreads();   // one barrier per lap, same as R8's per-CTA cost
        buf ^= 1;
        pair = next;
    }
}

extern "C" void kernel_launch(void* const* d_in, const int* in_sizes, int n_in,
                              void* d_out, int out_size)
{
    const float* x  = (const float*)d_in[0];   // [B,1,28,28]
    const float* W1 = (const float*)d_in[1];   // [32,4]
    const float* b1 = (const float*)d_in[2];   // [32]
    const float* W2 = (const float*)d_in[3];   // [10,32]
    const float* b2 = (const float*)d_in[4];   // [10]

    const int B      = in_sizes[0] / 784;      // 4096
    const int npairs = B / IPC;                // 2048

    float* out = (float*)d_out;                // [B,10] first
    float* adj = (float*)d_out + (size_t)B * NCLS;  // then [B,196,196]

    int sms = 148;
    cudaDeviceGetAttribute(&sms, cudaDevAttrMultiProcessorCount, 0);
    int grid = 2 * sms;                        // one wave, 2 CTAs/SM
    if (grid > npairs) grid = npairs;

    quanv_graph_kernel<<<grid, TPB>>>(x, W1, b1, W2, b2, out, adj, npairs, grid);
}